// round 1
// baseline (speedup 1.0000x reference)
#include <cuda_runtime.h>
#include <math.h>

#define F_DIM 256
#define N_MAX 200000
#define B_MAX 4000

// ---- scratch (device globals: allocation-free) ----
__device__ float g_kq[B_MAX * F_DIM];     // k_mol @ Wq  [B,256]
__device__ float g_kb[B_MAX];             // k_mol . bq  [B]
__device__ float g_vmol[B_MAX * F_DIM];   // v_mol       [B,256]
__device__ float g_a[N_MAX];              // softplus scores
__device__ float g_part[(N_MAX + 7) / 8]; // per-block partial sums
__device__ float g_inv[1];                // 1/(sum+eps)
__device__ float g_H[(size_t)N_MAX * F_DIM];
__device__ float g_Y[(size_t)N_MAX * F_DIM];

// ============================================================
// K1: per-molecule prep: e, k_mol, v_mol, kq = k_mol @ Wq, kb = k_mol . bq
// 16 molecules per block, 256 threads.
// ============================================================
__global__ void mol_prep(const float* __restrict__ E, const float* __restrict__ Wq,
                         const float* __restrict__ bq, const float* __restrict__ Wk,
                         const float* __restrict__ Wv, int B) {
    __shared__ float k_s[16][F_DIM];
    __shared__ float e_s[16][2], en_s[16][2];
    __shared__ float red[8];
    int tid = threadIdx.x;
    int b0  = blockIdx.x * 16;

    if (tid < 16) {
        int mol = b0 + tid;
        float Ev = (mol < B) ? E[mol] : 0.f;
        float e0 = fmaxf(Ev, 0.f), e1 = fmaxf(-Ev, 0.f);
        e_s[tid][0]  = e0;             e_s[tid][1]  = e1;
        // e / clip(e, 1.0) == min(e, 1) for e >= 0
        en_s[tid][0] = fminf(e0, 1.f); en_s[tid][1] = fminf(e1, 1.f);
    }
    __syncthreads();

    float wk0 = Wk[tid * 2], wk1 = Wk[tid * 2 + 1];
    float wv0 = Wv[tid * 2], wv1 = Wv[tid * 2 + 1];
    #pragma unroll
    for (int b = 0; b < 16; b++) {
        float kv = en_s[b][0] * wk0 + en_s[b][1] * wk1;
        k_s[b][tid] = kv;
        int mol = b0 + b;
        if (mol < B) g_vmol[mol * F_DIM + tid] = e_s[b][0] * wv0 + e_s[b][1] * wv1;
    }
    __syncthreads();

    // kq[b][c] = sum_f k_s[b][f] * Wq[f][c], c = tid (coalesced over Wq rows)
    float acc[16];
    #pragma unroll
    for (int b = 0; b < 16; b++) acc[b] = 0.f;
    for (int f = 0; f < F_DIM; f++) {
        float w = Wq[f * F_DIM + tid];
        #pragma unroll
        for (int b = 0; b < 16; b++) acc[b] += k_s[b][f] * w;
    }
    #pragma unroll
    for (int b = 0; b < 16; b++) {
        int mol = b0 + b;
        if (mol < B) g_kq[mol * F_DIM + tid] = acc[b];
    }

    // kb[b] = k_s[b] . bq  (block reduction)
    float bqv = bq[tid];
    int lane = tid & 31, wid = tid >> 5;
    for (int b = 0; b < 16; b++) {
        float v = k_s[b][tid] * bqv;
        #pragma unroll
        for (int o = 16; o > 0; o >>= 1) v += __shfl_down_sync(0xffffffffu, v, o);
        if (lane == 0) red[wid] = v;
        __syncthreads();
        if (tid == 0) {
            float s = 0.f;
            #pragma unroll
            for (int w = 0; w < 8; w++) s += red[w];
            int mol = b0 + b;
            if (mol < B) g_kb[mol] = s;
        }
        __syncthreads();
    }
}

// ============================================================
// K2: per-atom score: dot(x_n, kq[asi_n])/16 + kb -> softplus -> g_a,
// plus per-block partial sum (deterministic).
// 8 warps = 8 atoms per block.
// ============================================================
__global__ void atom_score(const float* __restrict__ x, const int* __restrict__ idx, int N) {
    __shared__ float wsum[8];
    int tid = threadIdx.x, lane = tid & 31, wid = tid >> 5;
    int n = blockIdx.x * 8 + wid;
    float a = 0.f;
    if (n < N) {
        int m = idx[n];
        const float* xr = x    + (size_t)n * F_DIM;
        const float* kq = g_kq + (size_t)m * F_DIM;
        float s = 0.f;
        #pragma unroll
        for (int j = 0; j < 8; j++) { int c = lane + j * 32; s += xr[c] * kq[c]; }
        #pragma unroll
        for (int o = 16; o > 0; o >>= 1) s += __shfl_down_sync(0xffffffffu, s, o);
        if (lane == 0) {
            float d = (s + g_kb[m]) * 0.0625f;              // 1/sqrt(256)
            a = fmaxf(d, 0.f) + log1pf(expf(-fabsf(d)));    // stable softplus
            g_a[n] = a;
        }
    }
    if (lane == 0) wsum[wid] = a;
    __syncthreads();
    if (tid == 0) {
        float t = 0.f;
        #pragma unroll
        for (int w = 0; w < 8; w++) t += wsum[w];
        g_part[blockIdx.x] = t;
    }
}

// K3: deterministic reduction of partials -> 1/(S + eps)
__global__ void reduce_part(int nparts) {
    __shared__ float red[256];
    int tid = threadIdx.x;
    float s = 0.f;
    for (int i = tid; i < nparts; i += 256) s += g_part[i];
    red[tid] = s;
    __syncthreads();
    for (int o = 128; o > 0; o >>= 1) {
        if (tid < o) red[tid] += red[tid + o];
        __syncthreads();
    }
    if (tid == 0) g_inv[0] = 1.f / (red[0] + 1e-8f);
}

// K4: H[n,f] = a_n * inv * v_mol[asi_n, f]   (float4 per thread)
__global__ void make_h(const int* __restrict__ idx, int N) {
    int g = blockIdx.x * blockDim.x + threadIdx.x;
    int total = N * (F_DIM / 4);
    if (g >= total) return;
    int n = g >> 6, f4 = g & 63;
    float sc = g_a[n] * g_inv[0];
    float4 v = ((const float4*)g_vmol)[(size_t)idx[n] * 64 + f4];
    float4 h = make_float4(sc * v.x, sc * v.y, sc * v.z, sc * v.w);
    ((float4*)g_H)[(size_t)n * 64 + f4] = h;
}

// ============================================================
// K5: C[n,f] (+)= sum_c swish(A[n,c]; al[c], be[c]) * W[f,c]
// 128x128 tile, BK=16, 256 threads, 8x8 per thread. Swish fused on A-load,
// residual add fused in epilogue. Buffer codes: 0=g_H, 1=g_Y, 2=out.
// ============================================================
__device__ __forceinline__ float* bufptr(int code, float* outp) {
    return (code == 0) ? g_H : (code == 1) ? g_Y : outp;
}

__global__ void __launch_bounds__(256, 2) gemm_swish(
    int Acode, const float* __restrict__ W,
    const float* __restrict__ al, const float* __restrict__ be,
    int Ccode, float* outp, int N, int accum) {
    __shared__ float As[16][128];
    __shared__ float Bs[16][128];
    __shared__ float sAl[256], sBe[256];

    const float* A = bufptr(Acode, outp);
    float*       C = bufptr(Ccode, outp);

    int tid = threadIdx.x;
    sAl[tid] = al[tid];
    sBe[tid] = be[tid];

    int m0 = blockIdx.x * 128;
    int n0 = blockIdx.y * 128;
    int ty = tid >> 4, tx = tid & 15;

    float acc[8][8];
    #pragma unroll
    for (int i = 0; i < 8; i++)
        #pragma unroll
        for (int j = 0; j < 8; j++) acc[i][j] = 0.f;

    for (int kt = 0; kt < 16; kt++) {
        int k0 = kt * 16;
        __syncthreads();   // prior compute done (and sAl/sBe visible on kt==0)
        #pragma unroll
        for (int qq = 0; qq < 2; qq++) {
            int q  = tid + qq * 256;           // 512 float4s per tile
            int r  = q >> 2;
            int cg = (q & 3) * 4;
            // --- A tile with fused swish ---
            int row = m0 + r;
            float4 av = make_float4(0.f, 0.f, 0.f, 0.f);
            if (row < N) av = *(const float4*)(A + (size_t)row * 256 + k0 + cg);
            float vals[4] = {av.x, av.y, av.z, av.w};
            #pragma unroll
            for (int j = 0; j < 4; j++) {
                int col = k0 + cg + j;
                float s  = sBe[col] * vals[j];
                float sw = sAl[col] * s * (1.f / (1.f + __expf(-s)));
                As[cg + j][r] = sw;
            }
            // --- W tile ---
            float4 wv = *(const float4*)(W + (size_t)(n0 + r) * 256 + k0 + cg);
            Bs[cg + 0][r] = wv.x; Bs[cg + 1][r] = wv.y;
            Bs[cg + 2][r] = wv.z; Bs[cg + 3][r] = wv.w;
        }
        __syncthreads();
        #pragma unroll
        for (int k = 0; k < 16; k++) {
            float a[8], b[8];
            *(float4*)(a)     = *(const float4*)&As[k][ty * 8];
            *(float4*)(a + 4) = *(const float4*)&As[k][ty * 8 + 4];
            *(float4*)(b)     = *(const float4*)&Bs[k][tx * 8];
            *(float4*)(b + 4) = *(const float4*)&Bs[k][tx * 8 + 4];
            #pragma unroll
            for (int i = 0; i < 8; i++)
                #pragma unroll
                for (int j = 0; j < 8; j++) acc[i][j] += a[i] * b[j];
        }
    }

    #pragma unroll
    for (int i = 0; i < 8; i++) {
        int row = m0 + ty * 8 + i;
        if (row >= N) continue;
        float* cp = C + (size_t)row * 256 + n0 + tx * 8;
        if (accum) {
            #pragma unroll
            for (int j = 0; j < 8; j++) cp[j] += acc[i][j];
        } else {
            *(float4*)(cp)     = make_float4(acc[i][0], acc[i][1], acc[i][2], acc[i][3]);
            *(float4*)(cp + 4) = make_float4(acc[i][4], acc[i][5], acc[i][6], acc[i][7]);
        }
    }
}

// ============================================================
extern "C" void kernel_launch(void* const* d_in, const int* in_sizes, int n_in,
                              void* d_out, int out_size) {
    const float* x    = (const float*)d_in[0];
    const float* E    = (const float*)d_in[1];
    const int*   asi  = (const int*)  d_in[2];
    const float* Wq   = (const float*)d_in[3];
    const float* bq   = (const float*)d_in[4];
    const float* Wk   = (const float*)d_in[5];
    const float* Wv   = (const float*)d_in[6];
    const float* W1   = (const float*)d_in[7];
    const float* W2   = (const float*)d_in[8];
    const float* a1   = (const float*)d_in[9];
    const float* b1   = (const float*)d_in[10];
    const float* a2   = (const float*)d_in[11];
    const float* b2   = (const float*)d_in[12];
    const float* oa   = (const float*)d_in[13];
    const float* ob   = (const float*)d_in[14];
    const float* Wout = (const float*)d_in[15];

    int B = in_sizes[1];
    int N = in_sizes[2];
    int R = in_sizes[7] / (F_DIM * F_DIM);
    float* out = (float*)d_out;

    mol_prep<<<(B + 15) / 16, 256>>>(E, Wq, bq, Wk, Wv, B);

    int gS = (N + 7) / 8;
    atom_score<<<gS, 256>>>(x, asi, N);
    reduce_part<<<1, 256>>>(gS);

    int tot4 = N * (F_DIM / 4);
    make_h<<<(tot4 + 255) / 256, 256>>>(asi, N);

    dim3 gg((N + 127) / 128, F_DIM / 128);
    for (int i = 0; i < R; i++) {
        gemm_swish<<<gg, 256>>>(0, W1 + (size_t)i * F_DIM * F_DIM,
                                a1 + i * F_DIM, b1 + i * F_DIM, 1, out, N, 0);
        gemm_swish<<<gg, 256>>>(1, W2 + (size_t)i * F_DIM * F_DIM,
                                a2 + i * F_DIM, b2 + i * F_DIM, 0, out, N, 1);
    }
    gemm_swish<<<gg, 256>>>(0, Wout, oa, ob, 2, out, N, 0);
}

// round 3
// speedup vs baseline: 1.9826x; 1.9826x over previous
#include <cuda_runtime.h>
#include <cuda_bf16.h>
#include <math.h>
#include <stdint.h>

#define F_DIM 256
#define N_MAX 200000
#define B_MAX 4000

// ---- scratch (device globals: allocation-free) ----
__device__ float g_kq[B_MAX * F_DIM];
__device__ float g_kb[B_MAX];
__device__ float g_vmol[B_MAX * F_DIM];
__device__ float g_a[N_MAX];
__device__ float g_part[(N_MAX + 7) / 8];
__device__ float g_inv[1];
__device__ float g_H[(size_t)N_MAX * F_DIM];
__device__ float g_Y[(size_t)N_MAX * F_DIM];
__device__ __nv_bfloat16 g_Whi[5 * F_DIM * F_DIM];  // weight hi, 5 slots
__device__ __nv_bfloat16 g_Wlo[5 * F_DIM * F_DIM];  // weight lo

// ============================================================
// warp-mma helpers (generic sm_80+ instructions: compile on sm_103)
// ============================================================
__device__ __forceinline__ uint32_t smem_u32(const void* p) {
    uint32_t a;
    asm("{ .reg .u64 t; cvta.to.shared.u64 t, %1; cvt.u32.u64 %0, t; }" : "=r"(a) : "l"(p));
    return a;
}
#define LDSM_X4(r, addr) \
    asm volatile("ldmatrix.sync.aligned.m8n8.x4.shared.b16 {%0,%1,%2,%3}, [%4];" \
        : "=r"((r)[0]), "=r"((r)[1]), "=r"((r)[2]), "=r"((r)[3]) : "r"(addr))
#define LDSM_X2(r, addr) \
    asm volatile("ldmatrix.sync.aligned.m8n8.x2.shared.b16 {%0,%1}, [%2];" \
        : "=r"((r)[0]), "=r"((r)[1]) : "r"(addr))
#define MMA_BF16(c, a, b) \
    asm volatile("mma.sync.aligned.m16n8k16.row.col.f32.bf16.bf16.f32 " \
        "{%0,%1,%2,%3}, {%4,%5,%6,%7}, {%8,%9}, {%0,%1,%2,%3};" \
        : "+f"((c)[0]), "+f"((c)[1]), "+f"((c)[2]), "+f"((c)[3]) \
        : "r"((a)[0]), "r"((a)[1]), "r"((a)[2]), "r"((a)[3]), "r"((b)[0]), "r"((b)[1]))

__device__ __forceinline__ uint32_t pack2bf(float x, float y) {
    __nv_bfloat16 bx = __float2bfloat16_rn(x), by = __float2bfloat16_rn(y);
    return ((uint32_t)__bfloat16_as_ushort(by) << 16) | (uint32_t)__bfloat16_as_ushort(bx);
}

// ============================================================
// K1: per-molecule prep (unchanged)
// ============================================================
__global__ void mol_prep(const float* __restrict__ E, const float* __restrict__ Wq,
                         const float* __restrict__ bq, const float* __restrict__ Wk,
                         const float* __restrict__ Wv, int B) {
    __shared__ float k_s[16][F_DIM];
    __shared__ float e_s[16][2], en_s[16][2];
    __shared__ float red[8];
    int tid = threadIdx.x;
    int b0  = blockIdx.x * 16;

    if (tid < 16) {
        int mol = b0 + tid;
        float Ev = (mol < B) ? E[mol] : 0.f;
        float e0 = fmaxf(Ev, 0.f), e1 = fmaxf(-Ev, 0.f);
        e_s[tid][0]  = e0;             e_s[tid][1]  = e1;
        en_s[tid][0] = fminf(e0, 1.f); en_s[tid][1] = fminf(e1, 1.f);
    }
    __syncthreads();

    float wk0 = Wk[tid * 2], wk1 = Wk[tid * 2 + 1];
    float wv0 = Wv[tid * 2], wv1 = Wv[tid * 2 + 1];
    #pragma unroll
    for (int b = 0; b < 16; b++) {
        float kv = en_s[b][0] * wk0 + en_s[b][1] * wk1;
        k_s[b][tid] = kv;
        int mol = b0 + b;
        if (mol < B) g_vmol[mol * F_DIM + tid] = e_s[b][0] * wv0 + e_s[b][1] * wv1;
    }
    __syncthreads();

    float acc[16];
    #pragma unroll
    for (int b = 0; b < 16; b++) acc[b] = 0.f;
    for (int f = 0; f < F_DIM; f++) {
        float w = Wq[f * F_DIM + tid];
        #pragma unroll
        for (int b = 0; b < 16; b++) acc[b] += k_s[b][f] * w;
    }
    #pragma unroll
    for (int b = 0; b < 16; b++) {
        int mol = b0 + b;
        if (mol < B) g_kq[mol * F_DIM + tid] = acc[b];
    }

    float bqv = bq[tid];
    int lane = tid & 31, wid = tid >> 5;
    for (int b = 0; b < 16; b++) {
        float v = k_s[b][tid] * bqv;
        #pragma unroll
        for (int o = 16; o > 0; o >>= 1) v += __shfl_down_sync(0xffffffffu, v, o);
        if (lane == 0) red[wid] = v;
        __syncthreads();
        if (tid == 0) {
            float s = 0.f;
            #pragma unroll
            for (int w = 0; w < 8; w++) s += red[w];
            int mol = b0 + b;
            if (mol < B) g_kb[mol] = s;
        }
        __syncthreads();
    }
}

// ============================================================
// K2 + K3: scores and normalization (unchanged)
// ============================================================
__global__ void atom_score(const float* __restrict__ x, const int* __restrict__ idx, int N) {
    __shared__ float wsum[8];
    int tid = threadIdx.x, lane = tid & 31, wid = tid >> 5;
    int n = blockIdx.x * 8 + wid;
    float a = 0.f;
    if (n < N) {
        int m = idx[n];
        const float* xr = x    + (size_t)n * F_DIM;
        const float* kq = g_kq + (size_t)m * F_DIM;
        float s = 0.f;
        #pragma unroll
        for (int j = 0; j < 8; j++) { int c = lane + j * 32; s += xr[c] * kq[c]; }
        #pragma unroll
        for (int o = 16; o > 0; o >>= 1) s += __shfl_down_sync(0xffffffffu, s, o);
        if (lane == 0) {
            float d = (s + g_kb[m]) * 0.0625f;
            a = fmaxf(d, 0.f) + log1pf(expf(-fabsf(d)));
            g_a[n] = a;
        }
    }
    if (lane == 0) wsum[wid] = a;
    __syncthreads();
    if (tid == 0) {
        float t = 0.f;
        #pragma unroll
        for (int w = 0; w < 8; w++) t += wsum[w];
        g_part[blockIdx.x] = t;
    }
}

__global__ void reduce_part(int nparts) {
    __shared__ float red[256];
    int tid = threadIdx.x;
    float s = 0.f;
    for (int i = tid; i < nparts; i += 256) s += g_part[i];
    red[tid] = s;
    __syncthreads();
    for (int o = 128; o > 0; o >>= 1) {
        if (tid < o) red[tid] += red[tid + o];
        __syncthreads();
    }
    if (tid == 0) g_inv[0] = 1.f / (red[0] + 1e-8f);
}

// ============================================================
// K4: weight split into bf16 hi/lo
// ============================================================
__global__ void wprep(const float* __restrict__ W, int slot) {
    int i = blockIdx.x * blockDim.x + threadIdx.x;
    if (i < F_DIM * F_DIM) {
        float w = W[i];
        __nv_bfloat16 hi = __float2bfloat16_rn(w);
        __nv_bfloat16 lo = __float2bfloat16_rn(w - __bfloat162float(hi));
        g_Whi[slot * F_DIM * F_DIM + i] = hi;
        g_Wlo[slot * F_DIM * F_DIM + i] = lo;
    }
}

// ============================================================
// K5: warp-mma bf16 split-3 GEMM.
// CTA: 128 rows x 256 cols, 512 threads (16 warps, 2m x 8n, warp 64x32).
// K chunked by 32, double-buffered smem, reg-prefetch of next chunk.
// A-source codes: 0=g_H, 1=g_Y, 3=virtual h (gather a*inv*vmol)
// C codes: 0=g_H, 1=g_Y, 2=out.  accmode: 0=store, 1=C+=acc, 2=C=gather_h+acc
// ============================================================
#define BK 32
#define NCHUNK (F_DIM / BK)
#define A_PITCH 80          // 32 halves (64B) + 16B pad
#define A_TILE  (128 * A_PITCH)   // 10240
#define B_TILE  (256 * A_PITCH)   // 20480
#define SM_AL   0
#define SM_BE   1024
#define SM_RSC  2048
#define SM_RM   2560
#define SM_A    4096                     // [db][hilo] x 10240  (40960)
#define SM_B    (4096 + 4 * A_TILE)      // [db][hilo] x 20480  (81920)
#define SM_TOTAL (SM_B + 4 * B_TILE)     // 126976 bytes

__global__ void __launch_bounds__(512, 1) gemm_tc(
    int Acode, int slot, const float* __restrict__ al, const float* __restrict__ be,
    int Ccode, int accmode, float* outp, const int* __restrict__ idx, int Nrows) {
    extern __shared__ char smem[];
    const uint32_t sb = smem_u32(smem);
    const int tid  = threadIdx.x;
    const int lane = tid & 31, wrp = tid >> 5;
    const int warpM = wrp >> 3, warpN = wrp & 7;   // 2 x 8
    const int m0 = blockIdx.x * 128;

    float* sAl  = (float*)(smem + SM_AL);
    float* sBe  = (float*)(smem + SM_BE);
    float* sRsc = (float*)(smem + SM_RSC);
    int*   sRm  = (int*)  (smem + SM_RM);

    if (tid < 256) { sAl[tid] = al[tid]; sBe[tid] = be[tid]; }
    if (tid < 128) {
        int grow = m0 + tid;
        if (grow < Nrows) { sRsc[tid] = g_a[grow] * g_inv[0]; sRm[tid] = idx[grow]; }
        else              { sRsc[tid] = 0.f; sRm[tid] = 0; }
    }
    __syncthreads();

    const float* Asrc = (Acode == 0) ? g_H : (Acode == 1) ? g_Y : (const float*)0;
    const __nv_bfloat16* Bhi = g_Whi + (size_t)slot * F_DIM * F_DIM;
    const __nv_bfloat16* Blo = g_Wlo + (size_t)slot * F_DIM * F_DIM;

    // per-thread load roles
    const int br = tid & 255;            // B row (output col)
    const int bs = tid >> 8;             // 0=hi, 1=lo
    const __nv_bfloat16* Bsrc = bs ? Blo : Bhi;

    float acc[4][4][4];
    #pragma unroll
    for (int i = 0; i < 4; i++)
        #pragma unroll
        for (int j = 0; j < 4; j++)
            #pragma unroll
            for (int l = 0; l < 4; l++) acc[i][j][l] = 0.f;

    // ---- prefetch (LDG only) ----
    float4 pa[2];
    uint4  pb[4];
    auto prefetch = [&](int c) {
        const int k0 = c * BK;
        #pragma unroll
        for (int i = 0; i < 2; i++) {
            int q = tid + i * 512;       // 0..1023
            int r = q >> 3, c4 = q & 7;
            int grow = m0 + r;
            float4 v = make_float4(0.f, 0.f, 0.f, 0.f);
            if (grow < Nrows) {
                if (Acode == 3)
                    v = ((const float4*)(g_vmol + (size_t)sRm[r] * F_DIM + k0))[c4];
                else
                    v = ((const float4*)(Asrc + (size_t)grow * F_DIM + k0))[c4];
            }
            pa[i] = v;
        }
        const uint4* wp = (const uint4*)(Bsrc + (size_t)br * F_DIM + k0);
        #pragma unroll
        for (int u = 0; u < 4; u++) pb[u] = wp[u];
    };
    // ---- store prefetched chunk to smem (with swish+split for A) ----
    auto stschunk = [&](int c, int db) {
        const int k0 = c * BK;
        char* ahd = smem + SM_A + (size_t)(db * 2 + 0) * A_TILE;
        char* ald = smem + SM_A + (size_t)(db * 2 + 1) * A_TILE;
        #pragma unroll
        for (int i = 0; i < 2; i++) {
            int q = tid + i * 512;
            int r = q >> 3, c4 = q & 7;
            float vals[4] = {pa[i].x, pa[i].y, pa[i].z, pa[i].w};
            float sc = (Acode == 3) ? sRsc[r] : 1.f;
            float hi[4], lo[4];
            #pragma unroll
            for (int j = 0; j < 4; j++) {
                int col = k0 + c4 * 4 + j;
                float xv = sc * vals[j];
                float s  = sBe[col] * xv;
                float sw = sAl[col] * s * (1.f / (1.f + __expf(-s)));
                __nv_bfloat16 bh = __float2bfloat16_rn(sw);
                hi[j] = __bfloat162float(bh);
                lo[j] = sw - hi[j];
            }
            uint32_t o = (uint32_t)(r * A_PITCH + c4 * 8);
            *(uint2*)(ahd + o) = make_uint2(pack2bf(hi[0], hi[1]), pack2bf(hi[2], hi[3]));
            *(uint2*)(ald + o) = make_uint2(pack2bf(lo[0], lo[1]), pack2bf(lo[2], lo[3]));
        }
        char* bd = smem + SM_B + (size_t)(db * 2 + bs) * B_TILE + (size_t)br * A_PITCH;
        #pragma unroll
        for (int u = 0; u < 4; u++) *(uint4*)(bd + u * 16) = pb[u];
    };

    // prologue
    prefetch(0);
    stschunk(0, 0);
    __syncthreads();

    const uint32_t aAddr0 = sb + SM_A + (uint32_t)(warpM * 64 + (lane & 15)) * A_PITCH + ((lane >> 4) * 16);
    const uint32_t bAddr0 = sb + SM_B + (uint32_t)(warpN * 32 + (lane & 7)) * A_PITCH + (((lane >> 3) & 1) * 16);

    for (int c = 0; c < NCHUNK; c++) {
        const int db = c & 1;
        if (c + 1 < NCHUNK) prefetch(c + 1);

        const uint32_t aB = aAddr0 + (uint32_t)(db * 2) * A_TILE;
        const uint32_t bB = bAddr0 + (uint32_t)(db * 2) * B_TILE;
        #pragma unroll
        for (int s = 0; s < 2; s++) {
            uint32_t bh[4][2], bl[4][2];
            #pragma unroll
            for (int nt = 0; nt < 4; nt++) {
                uint32_t ab = bB + nt * (8 * A_PITCH) + s * 32;
                LDSM_X2(bh[nt], ab);
                LDSM_X2(bl[nt], ab + B_TILE);
            }
            #pragma unroll
            for (int mt = 0; mt < 4; mt++) {
                uint32_t aa = aB + mt * (16 * A_PITCH) + s * 32;
                uint32_t ah[4], alr[4];
                LDSM_X4(ah, aa);
                LDSM_X4(alr, aa + A_TILE);
                #pragma unroll
                for (int nt = 0; nt < 4; nt++) {
                    MMA_BF16(acc[mt][nt], ah,  bh[nt]);
                    MMA_BF16(acc[mt][nt], ah,  bl[nt]);
                    MMA_BF16(acc[mt][nt], alr, bh[nt]);
                }
            }
        }
        if (c + 1 < NCHUNK) stschunk(c + 1, db ^ 1);
        __syncthreads();
    }

    // ---- epilogue ----
    float* Cp = (Ccode == 0) ? g_H : (Ccode == 1) ? g_Y : outp;
    const int rbase = warpM * 64 + (lane >> 2);
    const int cbase = warpN * 32 + (lane & 3) * 2;
    #pragma unroll
    for (int mt = 0; mt < 4; mt++) {
        #pragma unroll
        for (int rh = 0; rh < 2; rh++) {
            int lr = rbase + mt * 16 + rh * 8;
            int grow = m0 + lr;
            if (grow >= Nrows) continue;
            float* cp = Cp + (size_t)grow * F_DIM + cbase;
            float sc = 0.f; const float* vp = 0;
            if (accmode == 2) { sc = sRsc[lr]; vp = g_vmol + (size_t)sRm[lr] * F_DIM + cbase; }
            #pragma unroll
            for (int nt = 0; nt < 4; nt++) {
                float v0 = acc[mt][nt][rh * 2 + 0];
                float v1 = acc[mt][nt][rh * 2 + 1];
                float* dst = cp + nt * 8;
                if (accmode == 1) {
                    float2 o = *(float2*)dst;
                    v0 += o.x; v1 += o.y;
                } else if (accmode == 2) {
                    float2 o = *(const float2*)(vp + nt * 8);
                    v0 += sc * o.x; v1 += sc * o.y;
                }
                *(float2*)dst = make_float2(v0, v1);
            }
        }
    }
}

// ============================================================
extern "C" void kernel_launch(void* const* d_in, const int* in_sizes, int n_in,
                              void* d_out, int out_size) {
    const float* x    = (const float*)d_in[0];
    const float* E    = (const float*)d_in[1];
    const int*   asi  = (const int*)  d_in[2];
    const float* Wq   = (const float*)d_in[3];
    const float* bq   = (const float*)d_in[4];
    const float* Wk   = (const float*)d_in[5];
    const float* Wv   = (const float*)d_in[6];
    const float* W1   = (const float*)d_in[7];
    const float* W2   = (const float*)d_in[8];
    const float* a1   = (const float*)d_in[9];
    const float* b1   = (const float*)d_in[10];
    const float* a2   = (const float*)d_in[11];
    const float* b2   = (const float*)d_in[12];
    const float* oa   = (const float*)d_in[13];
    const float* ob   = (const float*)d_in[14];
    const float* Wout = (const float*)d_in[15];

    int B = in_sizes[1];
    int N = in_sizes[2];
    int R = in_sizes[7] / (F_DIM * F_DIM);
    float* out = (float*)d_out;

    cudaFuncSetAttribute(gemm_tc, cudaFuncAttributeMaxDynamicSharedMemorySize, SM_TOTAL);

    mol_prep<<<(B + 15) / 16, 256>>>(E, Wq, bq, Wk, Wv, B);

    int gS = (N + 7) / 8;
    atom_score<<<gS, 256>>>(x, asi, N);
    reduce_part<<<1, 256>>>(gS);

    for (int i = 0; i < R; i++) {
        wprep<<<F_DIM, 256>>>(W1 + (size_t)i * F_DIM * F_DIM, 2 * i);
        wprep<<<F_DIM, 256>>>(W2 + (size_t)i * F_DIM * F_DIM, 2 * i + 1);
    }
    wprep<<<F_DIM, 256>>>(Wout, 2 * R);

    int grid = (N + 127) / 128;
    // stage 0: virtual-h -> Y
    gemm_tc<<<grid, 512, SM_TOTAL>>>(3, 0, a1, b1, 1, 0, out, asi, N);
    // stage 1: Y -> H (= gather_h + acc)
    gemm_tc<<<grid, 512, SM_TOTAL>>>(1, 1, a2, b2, 0, 2, out, asi, N);
    for (int i = 1; i < R; i++) {
        gemm_tc<<<grid, 512, SM_TOTAL>>>(0, 2 * i,     a1 + i * F_DIM, b1 + i * F_DIM, 1, 0, out, asi, N);
        gemm_tc<<<grid, 512, SM_TOTAL>>>(1, 2 * i + 1, a2 + i * F_DIM, b2 + i * F_DIM, 0, 1, out, asi, N);
    }
    // final: H -> out
    gemm_tc<<<grid, 512, SM_TOTAL>>>(0, 2 * R, oa, ob, 2, 0, out, asi, N);
}

// round 4
// speedup vs baseline: 2.2722x; 1.1461x over previous
#include <cuda_runtime.h>
#include <cuda_bf16.h>
#include <math.h>
#include <stdint.h>

#define F_DIM 256
#define N_MAX 200000
#define B_MAX 4000

// ---- scratch (device globals: allocation-free) ----
__device__ float g_kq[B_MAX * F_DIM];
__device__ float g_kb[B_MAX];
__device__ float g_vmol[B_MAX * F_DIM];
__device__ float g_a[N_MAX];
__device__ float g_part[(N_MAX + 7) / 8];
__device__ float g_inv[1];
__device__ float g_H[(size_t)N_MAX * F_DIM];
__device__ float g_Y[(size_t)N_MAX * F_DIM];
__device__ __nv_bfloat16 g_Whi[5 * F_DIM * F_DIM];
__device__ __nv_bfloat16 g_Wlo[5 * F_DIM * F_DIM];

// ============================================================
// helpers
// ============================================================
__device__ __forceinline__ uint32_t smem_u32(const void* p) {
    uint32_t a;
    asm("{ .reg .u64 t; cvta.to.shared.u64 t, %1; cvt.u32.u64 %0, t; }" : "=r"(a) : "l"(p));
    return a;
}
#define LDSM_X4(r, addr) \
    asm volatile("ldmatrix.sync.aligned.m8n8.x4.shared.b16 {%0,%1,%2,%3}, [%4];" \
        : "=r"((r)[0]), "=r"((r)[1]), "=r"((r)[2]), "=r"((r)[3]) : "r"(addr))
#define MMA_BF16(c, a, b) \
    asm volatile("mma.sync.aligned.m16n8k16.row.col.f32.bf16.bf16.f32 " \
        "{%0,%1,%2,%3}, {%4,%5,%6,%7}, {%8,%9}, {%0,%1,%2,%3};" \
        : "+f"((c)[0]), "+f"((c)[1]), "+f"((c)[2]), "+f"((c)[3]) \
        : "r"((a)[0]), "r"((a)[1]), "r"((a)[2]), "r"((a)[3]), "r"((b)[0]), "r"((b)[1]))
#define CP_ASYNC16(dst, src) \
    asm volatile("cp.async.cg.shared.global [%0], [%1], 16;" :: "r"(dst), "l"(src))
#define CP_COMMIT() asm volatile("cp.async.commit_group;" ::: "memory")
#define CP_WAIT0()  asm volatile("cp.async.wait_group 0;" ::: "memory")

__device__ __forceinline__ uint32_t pack2bf(float x, float y) {
    __nv_bfloat16 bx = __float2bfloat16_rn(x), by = __float2bfloat16_rn(y);
    return ((uint32_t)__bfloat16_as_ushort(by) << 16) | (uint32_t)__bfloat16_as_ushort(bx);
}

// ============================================================
// K1: per-molecule prep (unchanged)
// ============================================================
__global__ void mol_prep(const float* __restrict__ E, const float* __restrict__ Wq,
                         const float* __restrict__ bq, const float* __restrict__ Wk,
                         const float* __restrict__ Wv, int B) {
    __shared__ float k_s[16][F_DIM];
    __shared__ float e_s[16][2], en_s[16][2];
    __shared__ float red[8];
    int tid = threadIdx.x;
    int b0  = blockIdx.x * 16;

    if (tid < 16) {
        int mol = b0 + tid;
        float Ev = (mol < B) ? E[mol] : 0.f;
        float e0 = fmaxf(Ev, 0.f), e1 = fmaxf(-Ev, 0.f);
        e_s[tid][0]  = e0;             e_s[tid][1]  = e1;
        en_s[tid][0] = fminf(e0, 1.f); en_s[tid][1] = fminf(e1, 1.f);
    }
    __syncthreads();

    float wk0 = Wk[tid * 2], wk1 = Wk[tid * 2 + 1];
    float wv0 = Wv[tid * 2], wv1 = Wv[tid * 2 + 1];
    #pragma unroll
    for (int b = 0; b < 16; b++) {
        float kv = en_s[b][0] * wk0 + en_s[b][1] * wk1;
        k_s[b][tid] = kv;
        int mol = b0 + b;
        if (mol < B) g_vmol[mol * F_DIM + tid] = e_s[b][0] * wv0 + e_s[b][1] * wv1;
    }
    __syncthreads();

    float acc[16];
    #pragma unroll
    for (int b = 0; b < 16; b++) acc[b] = 0.f;
    for (int f = 0; f < F_DIM; f++) {
        float w = Wq[f * F_DIM + tid];
        #pragma unroll
        for (int b = 0; b < 16; b++) acc[b] += k_s[b][f] * w;
    }
    #pragma unroll
    for (int b = 0; b < 16; b++) {
        int mol = b0 + b;
        if (mol < B) g_kq[mol * F_DIM + tid] = acc[b];
    }

    float bqv = bq[tid];
    int lane = tid & 31, wid = tid >> 5;
    for (int b = 0; b < 16; b++) {
        float v = k_s[b][tid] * bqv;
        #pragma unroll
        for (int o = 16; o > 0; o >>= 1) v += __shfl_down_sync(0xffffffffu, v, o);
        if (lane == 0) red[wid] = v;
        __syncthreads();
        if (tid == 0) {
            float s = 0.f;
            #pragma unroll
            for (int w = 0; w < 8; w++) s += red[w];
            int mol = b0 + b;
            if (mol < B) g_kb[mol] = s;
        }
        __syncthreads();
    }
}

// ============================================================
// K2 + K3 (unchanged)
// ============================================================
__global__ void atom_score(const float* __restrict__ x, const int* __restrict__ idx, int N) {
    __shared__ float wsum[8];
    int tid = threadIdx.x, lane = tid & 31, wid = tid >> 5;
    int n = blockIdx.x * 8 + wid;
    float a = 0.f;
    if (n < N) {
        int m = idx[n];
        const float* xr = x    + (size_t)n * F_DIM;
        const float* kq = g_kq + (size_t)m * F_DIM;
        float s = 0.f;
        #pragma unroll
        for (int j = 0; j < 8; j++) { int c = lane + j * 32; s += xr[c] * kq[c]; }
        #pragma unroll
        for (int o = 16; o > 0; o >>= 1) s += __shfl_down_sync(0xffffffffu, s, o);
        if (lane == 0) {
            float d = (s + g_kb[m]) * 0.0625f;
            a = fmaxf(d, 0.f) + log1pf(expf(-fabsf(d)));
            g_a[n] = a;
        }
    }
    if (lane == 0) wsum[wid] = a;
    __syncthreads();
    if (tid == 0) {
        float t = 0.f;
        #pragma unroll
        for (int w = 0; w < 8; w++) t += wsum[w];
        g_part[blockIdx.x] = t;
    }
}

__global__ void reduce_part(int nparts) {
    __shared__ float red[256];
    int tid = threadIdx.x;
    float s = 0.f;
    for (int i = tid; i < nparts; i += 256) s += g_part[i];
    red[tid] = s;
    __syncthreads();
    for (int o = 128; o > 0; o >>= 1) {
        if (tid < o) red[tid] += red[tid + o];
        __syncthreads();
    }
    if (tid == 0) g_inv[0] = 1.f / (red[0] + 1e-8f);
}

// ============================================================
// K4: all weights split into bf16 hi/lo in ONE launch
// slots: 2i = W1[i], 2i+1 = W2[i], 2R = Wout
// ============================================================
__global__ void wprep_all(const float* __restrict__ W1, const float* __restrict__ W2,
                          const float* __restrict__ Wout, int R) {
    int i = blockIdx.x * blockDim.x + threadIdx.x;
    int total = (2 * R + 1) * F_DIM * F_DIM;
    if (i >= total) return;
    int slot = i >> 16, j = i & 65535;
    const float* src = (slot == 2 * R) ? (Wout + j)
                     : (((slot & 1) ? W2 : W1) + (size_t)(slot >> 1) * 65536 + j);
    float w = *src;
    __nv_bfloat16 hi = __float2bfloat16_rn(w);
    __nv_bfloat16 lo = __float2bfloat16_rn(w - __bfloat162float(hi));
    g_Whi[i] = hi;
    g_Wlo[i] = lo;
}

// ============================================================
// K5: warp-mma bf16 split-3 GEMM, BK=64, cp.async B, x4 B-ldmatrix.
// CTA: 128 rows x 256 cols, 512 threads (16 warps: 2m x 8n, warp 64x32).
// ============================================================
#define BK 64
#define NCHUNK (F_DIM / BK)
#define PITCH 144                  // 128B data + 16B pad (conflict-free)
#define A_TILE (128 * PITCH)       // 18432
#define B_TILE (256 * PITCH)       // 36864
#define SM_AL   0
#define SM_BE   1024
#define SM_RSC  2048
#define SM_RM   2560
#define SM_A    4096                       // [db(2)][hilo(2)] x A_TILE = 73728
#define SM_B    (4096 + 4 * A_TILE)        // [db(2)][hilo(2)] x B_TILE = 147456
#define SM_TOTAL (SM_B + 4 * B_TILE)       // 225280 bytes

__global__ void __launch_bounds__(512, 1) gemm_tc(
    int Acode, int slot, const float* __restrict__ al, const float* __restrict__ be,
    int Ccode, int accmode, float* outp, const int* __restrict__ idx, int Nrows) {
    extern __shared__ char smem[];
    const uint32_t sb = smem_u32(smem);
    const int tid  = threadIdx.x;
    const int lane = tid & 31, wrp = tid >> 5;
    const int warpM = wrp >> 3, warpN = wrp & 7;   // 2 x 8
    const int m0 = blockIdx.x * 128;

    float* sAl  = (float*)(smem + SM_AL);
    float* sBe  = (float*)(smem + SM_BE);
    float* sRsc = (float*)(smem + SM_RSC);
    int*   sRm  = (int*)  (smem + SM_RM);

    if (tid < 256) { sAl[tid] = al[tid]; sBe[tid] = be[tid]; }
    if (tid < 128) {
        int grow = m0 + tid;
        if (grow < Nrows) { sRsc[tid] = g_a[grow] * g_inv[0]; sRm[tid] = idx[grow]; }
        else              { sRsc[tid] = 0.f; sRm[tid] = 0; }
    }
    __syncthreads();

    const float* Asrc = (Acode == 0) ? g_H : (Acode == 1) ? g_Y : (const float*)0;
    const __nv_bfloat16* Bbase[2] = { g_Whi + (size_t)slot * 65536, g_Wlo + (size_t)slot * 65536 };

    float acc[4][4][4];
    #pragma unroll
    for (int i = 0; i < 4; i++)
        #pragma unroll
        for (int j = 0; j < 4; j++)
            #pragma unroll
            for (int l = 0; l < 4; l++) acc[i][j][l] = 0.f;

    // ---- B: cp.async gmem->smem, 8 x 16B per thread per chunk ----
    auto cpB = [&](int c, int db) {
        const int k0 = c * BK;
        #pragma unroll
        for (int i = 0; i < 8; i++) {
            int t   = tid + i * 512;        // 0..4095
            int sp  = t >> 11;              // 0=hi, 1=lo
            int w   = t & 2047;
            int row = w >> 3, c16 = w & 7;
            const __nv_bfloat16* src = Bbase[sp] + (size_t)row * F_DIM + k0 + c16 * 8;
            uint32_t dst = sb + SM_B + (uint32_t)(db * 2 + sp) * B_TILE
                         + (uint32_t)row * PITCH + c16 * 16;
            CP_ASYNC16(dst, src);
        }
        CP_COMMIT();
    };

    // ---- A: LDG prefetch (4 float4 / thread) ----
    float4 pa[4];
    auto prefetchA = [&](int c) {
        const int k0 = c * BK;
        #pragma unroll
        for (int i = 0; i < 4; i++) {
            int q = tid + i * 512;          // 0..2047
            int r = q >> 4, c4 = q & 15;    // 16 float4 per row
            int grow = m0 + r;
            float4 v = make_float4(0.f, 0.f, 0.f, 0.f);
            if (grow < Nrows) {
                if (Acode == 3)
                    v = ((const float4*)(g_vmol + (size_t)sRm[r] * F_DIM + k0))[c4];
                else
                    v = ((const float4*)(Asrc + (size_t)grow * F_DIM + k0))[c4];
            }
            pa[i] = v;
        }
    };
    // ---- A: swish + split + store to smem ----
    auto stsA = [&](int c, int db) {
        const int k0 = c * BK;
        char* ahd = smem + SM_A + (size_t)(db * 2 + 0) * A_TILE;
        char* ald = smem + SM_A + (size_t)(db * 2 + 1) * A_TILE;
        #pragma unroll
        for (int i = 0; i < 4; i++) {
            int q = tid + i * 512;
            int r = q >> 4, c4 = q & 15;
            float vals[4] = {pa[i].x, pa[i].y, pa[i].z, pa[i].w};
            float sc = (Acode == 3) ? sRsc[r] : 1.f;
            float hi[4], lo[4];
            #pragma unroll
            for (int j = 0; j < 4; j++) {
                int col = k0 + c4 * 4 + j;
                float xv = sc * vals[j];
                float s  = sBe[col] * xv;
                float sw = sAl[col] * s * (1.f / (1.f + __expf(-s)));
                __nv_bfloat16 bh = __float2bfloat16_rn(sw);
                hi[j] = __bfloat162float(bh);
                lo[j] = sw - hi[j];
            }
            uint32_t o = (uint32_t)(r * PITCH + c4 * 8);
            *(uint2*)(ahd + o) = make_uint2(pack2bf(hi[0], hi[1]), pack2bf(hi[2], hi[3]));
            *(uint2*)(ald + o) = make_uint2(pack2bf(lo[0], lo[1]), pack2bf(lo[2], lo[3]));
        }
    };

    // prologue: chunk 0
    cpB(0, 0);
    prefetchA(0);
    stsA(0, 0);
    CP_WAIT0();
    __syncthreads();

    const uint32_t aAddr0 = sb + SM_A + (uint32_t)(warpM * 64 + (lane & 15)) * PITCH
                          + ((lane >> 4) * 16);
    const uint32_t bAddr0 = sb + SM_B
                          + (uint32_t)(warpN * 32 + (lane & 7) + ((lane >> 4) << 3)) * PITCH
                          + (((lane >> 3) & 1) * 16);

    for (int c = 0; c < NCHUNK; c++) {
        const int db = c & 1;
        if (c + 1 < NCHUNK) { cpB(c + 1, db ^ 1); prefetchA(c + 1); }

        const uint32_t aB = aAddr0 + (uint32_t)(db * 2) * A_TILE;
        const uint32_t bB = bAddr0 + (uint32_t)(db * 2) * B_TILE;
        #pragma unroll
        for (int s = 0; s < 4; s++) {
            uint32_t bh[4][2], bl[4][2];
            #pragma unroll
            for (int ntp = 0; ntp < 2; ntp++) {
                uint32_t t4[4];
                uint32_t ab = bB + ntp * (16 * PITCH) + s * 32;
                LDSM_X4(t4, ab);
                bh[2*ntp][0] = t4[0]; bh[2*ntp][1] = t4[1];
                bh[2*ntp+1][0] = t4[2]; bh[2*ntp+1][1] = t4[3];
                LDSM_X4(t4, ab + B_TILE);
                bl[2*ntp][0] = t4[0]; bl[2*ntp][1] = t4[1];
                bl[2*ntp+1][0] = t4[2]; bl[2*ntp+1][1] = t4[3];
            }
            #pragma unroll
            for (int mt = 0; mt < 4; mt++) {
                uint32_t aa = aB + mt * (16 * PITCH) + s * 32;
                uint32_t ah[4], alr[4];
                LDSM_X4(ah, aa);
                LDSM_X4(alr, aa + A_TILE);
                #pragma unroll
                for (int nt = 0; nt < 4; nt++) {
                    MMA_BF16(acc[mt][nt], ah,  bh[nt]);
                    MMA_BF16(acc[mt][nt], ah,  bl[nt]);
                    MMA_BF16(acc[mt][nt], alr, bh[nt]);
                }
            }
        }
        if (c + 1 < NCHUNK) { stsA(c + 1, db ^ 1); CP_WAIT0(); }
        __syncthreads();
    }

    // ---- epilogue ----
    float* Cp = (Ccode == 0) ? g_H : (Ccode == 1) ? g_Y : outp;
    const int rbase = warpM * 64 + (lane >> 2);
    const int cbase = warpN * 32 + (lane & 3) * 2;
    #pragma unroll
    for (int mt = 0; mt < 4; mt++) {
        #pragma unroll
        for (int rh = 0; rh < 2; rh++) {
            int lr = rbase + mt * 16 + rh * 8;
            int grow = m0 + lr;
            if (grow >= Nrows) continue;
            float* cp = Cp + (size_t)grow * F_DIM + cbase;
            float sc = 0.f; const float* vp = 0;
            if (accmode == 2) { sc = sRsc[lr]; vp = g_vmol + (size_t)sRm[lr] * F_DIM + cbase; }
            #pragma unroll
            for (int nt = 0; nt < 4; nt++) {
                float v0 = acc[mt][nt][rh * 2 + 0];
                float v1 = acc[mt][nt][rh * 2 + 1];
                float* dst = cp + nt * 8;
                if (accmode == 1) {
                    float2 o = *(float2*)dst;
                    v0 += o.x; v1 += o.y;
                } else if (accmode == 2) {
                    float2 o = *(const float2*)(vp + nt * 8);
                    v0 += sc * o.x; v1 += sc * o.y;
                }
                *(float2*)dst = make_float2(v0, v1);
            }
        }
    }
}

// ============================================================
extern "C" void kernel_launch(void* const* d_in, const int* in_sizes, int n_in,
                              void* d_out, int out_size) {
    const float* x    = (const float*)d_in[0];
    const float* E    = (const float*)d_in[1];
    const int*   asi  = (const int*)  d_in[2];
    const float* Wq   = (const float*)d_in[3];
    const float* bq   = (const float*)d_in[4];
    const float* Wk   = (const float*)d_in[5];
    const float* Wv   = (const float*)d_in[6];
    const float* W1   = (const float*)d_in[7];
    const float* W2   = (const float*)d_in[8];
    const float* a1   = (const float*)d_in[9];
    const float* b1   = (const float*)d_in[10];
    const float* a2   = (const float*)d_in[11];
    const float* b2   = (const float*)d_in[12];
    const float* oa   = (const float*)d_in[13];
    const float* ob   = (const float*)d_in[14];
    const float* Wout = (const float*)d_in[15];

    int B = in_sizes[1];
    int N = in_sizes[2];
    int R = in_sizes[7] / (F_DIM * F_DIM);
    float* out = (float*)d_out;

    cudaFuncSetAttribute(gemm_tc, cudaFuncAttributeMaxDynamicSharedMemorySize, SM_TOTAL);

    mol_prep<<<(B + 15) / 16, 256>>>(E, Wq, bq, Wk, Wv, B);         // launch 0

    int gS = (N + 7) / 8;
    atom_score<<<gS, 256>>>(x, asi, N);                              // launch 1
    reduce_part<<<1, 256>>>(gS);                                     // launch 2

    int wtot = (2 * R + 1) * F_DIM * F_DIM;
    wprep_all<<<(wtot + 255) / 256, 256>>>(W1, W2, Wout, R);         // launch 3

    int grid = (N + 127) / 128;
    // stage 0: virtual-h -> Y                                          launch 4
    gemm_tc<<<grid, 512, SM_TOTAL>>>(3, 0, a1, b1, 1, 0, out, asi, N);
    // stage 1: Y -> H (= gather_h + acc)                               launch 5 (ncu -s 5)
    gemm_tc<<<grid, 512, SM_TOTAL>>>(1, 1, a2, b2, 0, 2, out, asi, N);
    for (int i = 1; i < R; i++) {
        gemm_tc<<<grid, 512, SM_TOTAL>>>(0, 2 * i,     a1 + i * F_DIM, b1 + i * F_DIM, 1, 0, out, asi, N);
        gemm_tc<<<grid, 512, SM_TOTAL>>>(1, 2 * i + 1, a2 + i * F_DIM, b2 + i * F_DIM, 0, 1, out, asi, N);
    }
    gemm_tc<<<grid, 512, SM_TOTAL>>>(0, 2 * R, oa, ob, 2, 0, out, asi, N);
}